// round 7
// baseline (speedup 1.0000x reference)
#include <cuda_runtime.h>
#include <cuda_bf16.h>
#include <math.h>

#define BB 8
#define IMG 256
#define INCH 2
#define PSZ 16
#define EE 256
#define DEPTH 8
#define HPN 16
#define LL 256
#define DI 512
#define DS 16
#define DTRN 16
#define DCN 4
#define NTOK 2048          // B*L
#define XZW 1024           // 2*DI

// ---------------- scratch ----------------
__device__ float g_temb[BB*EE];
__device__ float g_h[NTOK*EE];
__device__ float g_patches[NTOK*512];   // also reused as row-major y after ssm
__device__ float g_xz[NTOK*XZW];
__device__ float g_ut[BB*DI*LL];    // u transposed [b][d][t]
__device__ float g_dtt[BB*DI*LL];   // dt transposed [b][d][t]
__device__ float g_zs[BB*DI*LL];    // silu(z) transposed [b][d][t]
__device__ float g_bc[NTOK*32];     // B[16],C[16] per token
__device__ float g_yt[BB*DI*LL];    // y transposed [b][d][t]
__device__ float g_feat[BB*EE*HPN*HPN];
__device__ float g_d1[BB*128*32*32];
__device__ float g_d2[BB*64*64*64];
__device__ float g_d3[BB*32*128*128];

__device__ __forceinline__ float geluf(float v){ return 0.5f*v*(1.0f+erff(v*0.70710678118654752f)); }
__device__ __forceinline__ float siluf(float v){ return v/(1.0f+__expf(-v)); }

__device__ __forceinline__ void mma16(float* d, const unsigned* a, unsigned b0, unsigned b1){
  asm volatile("mma.sync.aligned.m16n8k16.row.col.f32.bf16.bf16.f32 "
    "{%0,%1,%2,%3}, {%4,%5,%6,%7}, {%8,%9}, {%0,%1,%2,%3};"
    : "+f"(d[0]),"+f"(d[1]),"+f"(d[2]),"+f"(d[3])
    : "r"(a[0]),"r"(a[1]),"r"(a[2]),"r"(a[3]), "r"(b0),"r"(b1));
}
__device__ __forceinline__ void ldsm4(unsigned& r0, unsigned& r1, unsigned& r2, unsigned& r3, unsigned addr){
  asm volatile("ldmatrix.sync.aligned.m8n8.x4.shared.b16 {%0,%1,%2,%3}, [%4];"
    : "=r"(r0),"=r"(r1),"=r"(r2),"=r"(r3) : "r"(addr) : "memory");
}

// split float4 (4 consecutive k) into bf16 hi/lo packed pairs
__device__ __forceinline__ void store_split(unsigned* baseHi, unsigned* baseLo, int idx, float4 v){
  __nv_bfloat162 h0 = __floats2bfloat162_rn(v.x, v.y);
  __nv_bfloat162 h1 = __floats2bfloat162_rn(v.z, v.w);
  float r0 = v.x - __bfloat162float(h0.x);
  float r1 = v.y - __bfloat162float(h0.y);
  float r2 = v.z - __bfloat162float(h1.x);
  float r3 = v.w - __bfloat162float(h1.y);
  __nv_bfloat162 l0 = __floats2bfloat162_rn(r0, r1);
  __nv_bfloat162 l1 = __floats2bfloat162_rn(r2, r3);
  uint2 hw, lw;
  hw.x = *(unsigned*)&h0; hw.y = *(unsigned*)&h1;
  lw.x = *(unsigned*)&l0; lw.y = *(unsigned*)&l1;
  *(uint2*)(baseHi + idx) = hw;
  *(uint2*)(baseLo + idx) = lw;
}

// ---------------- time embedding ----------------
__global__ void time_emb_kernel(const int* __restrict__ t, const float* __restrict__ w1,
                                const float* __restrict__ b1, const float* __restrict__ w2,
                                const float* __restrict__ b2){
  __shared__ float hdn[EE];
  int b = blockIdx.x; int j = threadIdx.x;
  float tf = (float)t[b];
  hdn[j] = geluf(tf*w1[j] + b1[j]);
  __syncthreads();
  float acc = b2[j];
  #pragma unroll 8
  for (int k=0;k<EE;k++) acc = fmaf(hdn[k], w2[k*EE + j], acc);
  g_temb[b*EE + j] = acc;
}

// ---------------- im2col patch gather ----------------
__global__ void patch_gather_kernel(const float* __restrict__ x){
  int idx = blockIdx.x*blockDim.x + threadIdx.x;
  int k = idx & 511; int tok = idx >> 9;
  int l = tok & (LL-1); int b = tok >> 8;
  int c = k >> 8; int rem = k & 255; int p = rem >> 4; int q = rem & 15;
  int hp = l >> 4; int wp = l & 15;
  g_patches[idx] = x[(((size_t)(b*INCH + c))*IMG + hp*PSZ + p)*IMG + wp*PSZ + q];
}

// ================= bf16x3 tensor-core GEMM (ldmatrix frags) =================
// C[M,N] = A[M,K] @ W[N,K]^T. Block (64*MTILES)x64, BK=32, 8 warps (4m x 2n).
// smem words pack bf16 k-pairs; hi/lo planes; [m][kp] pitch 20 (ldmatrix conflict-free).
// ASRC: 0 = plain row-major A; 1 = fused LayerNorm on A rows (lng/lnb)
// EPI : 0 = plain; 1 = +bias+pos+temb; 2 = += C (residual)
#define B_SZ (64*20)
#define SMEM_BM64  ((4*64*20 + 4*B_SZ)*4)
#define SMEM_BM128 ((4*128*20 + 4*B_SZ)*4 + 256*4)
template<int MTILES,int ASRC,int EPI>
__global__ void __launch_bounds__(256)
mma_gemm(const float* __restrict__ A, const float* __restrict__ W,
         const float* __restrict__ lng, const float* __restrict__ lnb,
         const float* __restrict__ bias, const float* __restrict__ pos,
         const float* __restrict__ temb, float* __restrict__ C,
         int K, int N)
{
  constexpr int BM = 64*MTILES;
  constexpr int A_SZ = BM*20;
  extern __shared__ unsigned smem_u[];
  unsigned* uA = smem_u;                       // [buf][plane][m][kp]
  unsigned* uB = smem_u + 4*A_SZ;              // [buf][plane][n][kp]
  float* s_mu = (float*)(smem_u + 4*A_SZ + 4*B_SZ);
  float* s_rs = s_mu + 128;

  const int tid = threadIdx.x;
  const int m0 = blockIdx.y*BM, n0 = blockIdx.x*64;

  if (ASRC==1){
    int r = tid>>1, hf = tid&1;
    const float4* row = (const float4*)(A + (size_t)(m0+r)*K + hf*(K/2));
    float s=0.f, sq=0.f;
    for (int i=0;i<K/8;i++){ float4 v=row[i];
      s += v.x+v.y+v.z+v.w; sq += v.x*v.x+v.y*v.y+v.z*v.z+v.w*v.w; }
    s  += __shfl_xor_sync(0xffffffffu, s, 1);
    sq += __shfl_xor_sync(0xffffffffu, sq, 1);
    if (!hf){
      float muv = s/(float)K;
      float var = sq/(float)K - muv*muv;
      s_mu[r]=muv; s_rs[r]=rsqrtf(var+1e-5f);
    }
    __syncthreads();
  }

  // loader coords
  const int amr = tid>>3;            // A row base (0..31), +i*32
  const int akc = (tid&7)*4;         // k offset within chunk
  const int akp = akc>>1;            // kpair index
  const int NK = K/32;

  // initial chunk 0 (buf 0: hi at 0, lo at +A_SZ/B_SZ)
  {
    float4 g4, b4;
    if (ASRC==1){ g4 = *(const float4*)(lng+akc); b4 = *(const float4*)(lnb+akc); }
    #pragma unroll
    for (int i=0;i<BM/32;i++){
      int m = amr + i*32;
      float4 v = *(const float4*)(A + (size_t)(m0+m)*K + akc);
      if (ASRC==1){
        float mu = s_mu[m], rs = s_rs[m];
        v.x=(v.x-mu)*rs*g4.x+b4.x; v.y=(v.y-mu)*rs*g4.y+b4.y;
        v.z=(v.z-mu)*rs*g4.z+b4.z; v.w=(v.w-mu)*rs*g4.w+b4.w;
      }
      store_split(uA, uA + A_SZ, m*20 + akp, v);
    }
    #pragma unroll
    for (int i=0;i<2;i++){
      int p = tid + i*256;
      int n = p>>3, kc4 = (p&7)*4;
      float4 v = *(const float4*)(W + (size_t)(n0+n)*K + kc4);
      store_split(uB, uB + B_SZ, n*20 + (kc4>>1), v);
    }
  }
  __syncthreads();

  const int lane = tid&31, wid = tid>>5;
  const int wm = (wid>>1)*(16*MTILES), wn = (wid&1)*32;
  const int g = lane>>2, tg = lane&3;
  float acc[MTILES][4][4] = {};

  // ldmatrix lane-address components
  const unsigned sb  = (unsigned)__cvta_generic_to_shared(smem_u);
  const unsigned sbB = sb + 16*A_SZ;                    // 4*A_SZ words * 4B
  const int aRow = wm + (lane&15);
  const int aKp  = (lane>>4)*4;
  const int bRow = wn + ((lane>>4)&1)*8 + (lane&7);
  const int bKp  = ((lane>>3)&1)*4;

  float4 pa[BM/32], pb[2], pg4, pb4;
  for (int ks=0; ks<NK; ks++){
    const int buf = ks&1;
    if (ks+1 < NK){
      int k0 = (ks+1)*32;
      if (ASRC==1){ pg4 = *(const float4*)(lng+k0+akc); pb4 = *(const float4*)(lnb+k0+akc); }
      #pragma unroll
      for (int i=0;i<BM/32;i++)
        pa[i] = *(const float4*)(A + (size_t)(m0+amr+i*32)*K + k0 + akc);
      #pragma unroll
      for (int i=0;i<2;i++){
        int p = tid + i*256;
        pb[i] = *(const float4*)(W + (size_t)(n0+(p>>3))*K + k0 + (p&7)*4);
      }
    }
    const unsigned aH = sb  + (buf*2+0)*A_SZ*4;
    const unsigned aL = sb  + (buf*2+1)*A_SZ*4;
    const unsigned bH = sbB + (buf*2+0)*B_SZ*4;
    const unsigned bL = sbB + (buf*2+1)*B_SZ*4;
    #pragma unroll
    for (int h=0; h<2; h++){
      const int kb = h*8;
      unsigned bh[4][2], bl[4][2];
      #pragma unroll
      for (int np=0;np<2;np++){
        unsigned off = ((bRow + np*16)*20 + kb + bKp)*4;
        ldsm4(bh[2*np][0], bh[2*np][1], bh[2*np+1][0], bh[2*np+1][1], bH + off);
        ldsm4(bl[2*np][0], bl[2*np][1], bl[2*np+1][0], bl[2*np+1][1], bL + off);
      }
      #pragma unroll
      for (int mt=0;mt<MTILES;mt++){
        unsigned off = ((aRow + mt*16)*20 + kb + aKp)*4;
        unsigned ah[4], al[4];
        ldsm4(ah[0], ah[1], ah[2], ah[3], aH + off);
        ldsm4(al[0], al[1], al[2], al[3], aL + off);
        #pragma unroll
        for (int nt=0;nt<4;nt++){
          mma16(acc[mt][nt], ah, bh[nt][0], bh[nt][1]);
          mma16(acc[mt][nt], al, bh[nt][0], bh[nt][1]);
          mma16(acc[mt][nt], ah, bl[nt][0], bl[nt][1]);
        }
      }
    }
    if (ks+1 < NK){
      const int nb2 = buf^1;
      unsigned* dAh = uA + (nb2*2+0)*A_SZ;
      unsigned* dAl = uA + (nb2*2+1)*A_SZ;
      unsigned* dBh = uB + (nb2*2+0)*B_SZ;
      unsigned* dBl = uB + (nb2*2+1)*B_SZ;
      #pragma unroll
      for (int i=0;i<BM/32;i++){
        int m = amr + i*32;
        float4 v = pa[i];
        if (ASRC==1){
          float mu = s_mu[m], rs = s_rs[m];
          v.x=(v.x-mu)*rs*pg4.x+pb4.x; v.y=(v.y-mu)*rs*pg4.y+pb4.y;
          v.z=(v.z-mu)*rs*pg4.z+pb4.z; v.w=(v.w-mu)*rs*pg4.w+pb4.w;
        }
        store_split(dAh, dAl, m*20 + akp, v);
      }
      #pragma unroll
      for (int i=0;i<2;i++){
        int p = tid + i*256;
        store_split(dBh, dBl, (p>>3)*20 + ((p&7)*4>>1), pb[i]);
      }
    }
    __syncthreads();
  }

  // epilogue
  #pragma unroll
  for (int mt=0;mt<MTILES;mt++){
    #pragma unroll
    for (int nt=0;nt<4;nt++){
      int row = m0 + wm + mt*16 + g;
      int col = n0 + wn + nt*8 + tg*2;
      float2 v0 = make_float2(acc[mt][nt][0], acc[mt][nt][1]);
      float2 v1 = make_float2(acc[mt][nt][2], acc[mt][nt][3]);
      if (EPI==1){
        int l0i = row & 255, b0i = row >> 8;
        int l1i = (row+8) & 255, b1i = (row+8) >> 8;
        v0.x += bias[col]   + pos[(size_t)l0i*EE+col]   + temb[(size_t)b0i*EE+col];
        v0.y += bias[col+1] + pos[(size_t)l0i*EE+col+1] + temb[(size_t)b0i*EE+col+1];
        v1.x += bias[col]   + pos[(size_t)l1i*EE+col]   + temb[(size_t)b1i*EE+col];
        v1.y += bias[col+1] + pos[(size_t)l1i*EE+col+1] + temb[(size_t)b1i*EE+col+1];
      } else if (EPI==2){
        float2 o0 = *(float2*)(C + (size_t)row*N + col);
        float2 o1 = *(float2*)(C + (size_t)(row+8)*N + col);
        v0.x += o0.x; v0.y += o0.y; v1.x += o1.x; v1.y += o1.y;
      }
      *(float2*)(C + (size_t)row*N + col) = v0;
      *(float2*)(C + (size_t)(row+8)*N + col) = v1;
    }
  }
}

// ---------------- fused prep: causal-conv+SiLU, z-SiLU, x_proj, dt; transposed stores ----
__global__ void prep_kernel(const float* __restrict__ cw, const float* __restrict__ cb,
                            const float* __restrict__ xw,   // [48][512]
                            const float* __restrict__ dtw,  // [512][16]
                            const float* __restrict__ dtb){ // [512]
  __shared__ float us[8][513];
  __shared__ float pool[48*129];
  __shared__ float dbc_s[8][52];
  const int tid = threadIdx.x;            // 256
  const int b  = blockIdx.x >> 5;
  const int l0 = (blockIdx.x & 31) * 8;
  float* zsm = pool;
  #pragma unroll
  for (int r=0;r<16;r++){
    int idx = r*256 + tid;
    int d  = idx & 511;
    int ti = idx >> 9;
    int l  = l0 + ti;
    float acc = cb[d];
    #pragma unroll
    for (int j=0;j<4;j++){
      int ls = l + j - 3;
      if (ls >= 0) acc = fmaf(g_xz[((size_t)(b*LL + ls))*XZW + d], cw[d*4 + j], acc);
    }
    us[ti][d] = siluf(acc);
    float z = g_xz[((size_t)(b*LL + l))*XZW + DI + d];
    zsm[ti*516 + d] = siluf(z);
  }
  __syncthreads();
  #pragma unroll
  for (int rr=0;rr<2;rr++){
    int d = tid + rr*256;
    float4 v0, v1, w0, w1;
    v0.x=us[0][d]; v0.y=us[1][d]; v0.z=us[2][d]; v0.w=us[3][d];
    v1.x=us[4][d]; v1.y=us[5][d]; v1.z=us[6][d]; v1.w=us[7][d];
    w0.x=zsm[0*516+d]; w0.y=zsm[1*516+d]; w0.z=zsm[2*516+d]; w0.w=zsm[3*516+d];
    w1.x=zsm[4*516+d]; w1.y=zsm[5*516+d]; w1.z=zsm[6*516+d]; w1.w=zsm[7*516+d];
    float* up = g_ut + ((size_t)(b*DI + d))*LL + l0;
    *(float4*)up = v0; *(float4*)(up+4) = v1;
    float* zp = g_zs + ((size_t)(b*DI + d))*LL + l0;
    *(float4*)zp = w0; *(float4*)(zp+4) = w1;
  }
  const int ti = tid >> 5, lane = tid & 31;
  float accA = 0.f, accB = 0.f;
  for (int kt=0;kt<4;kt++){
    __syncthreads();
    #pragma unroll
    for (int i=0;i<6;i++){
      int f = (tid + i*256)*4;
      int j = f >> 7, c = f & 127;
      float4 v = *(const float4*)(xw + (size_t)j*DI + kt*128 + c);
      pool[j*129+c]=v.x; pool[j*129+c+1]=v.y; pool[j*129+c+2]=v.z; pool[j*129+c+3]=v.w;
    }
    __syncthreads();
    #pragma unroll 4
    for (int c=0;c<128;c++){
      float a = us[ti][kt*128 + c];
      accA = fmaf(a, pool[lane*129 + c], accA);
      if (lane < 16) accB = fmaf(a, pool[(32+lane)*129 + c], accB);
    }
  }
  __syncthreads();
  dbc_s[ti][lane] = accA;
  if (lane < 16) dbc_s[ti][32 + lane] = accB;
  __syncthreads();
  {
    int tti = tid >> 5, jj = tid & 31;
    g_bc[((size_t)(b*LL) + l0 + tti)*32 + jj] = dbc_s[tti][16 + jj];
  }
  #pragma unroll
  for (int r=0;r<16;r++){
    int idx = r*256 + tid;
    int d  = idx & 511;
    int ti2 = idx >> 9;
    const float* dbp = dbc_s[ti2];
    const float4* dw4 = (const float4*)(dtw + (size_t)d*16);
    float4 w0 = dw4[0], w1 = dw4[1], w2 = dw4[2], w3 = dw4[3];
    float acc = dtb[d];
    acc=fmaf(dbp[0],w0.x,acc);  acc=fmaf(dbp[1],w0.y,acc);  acc=fmaf(dbp[2],w0.z,acc);  acc=fmaf(dbp[3],w0.w,acc);
    acc=fmaf(dbp[4],w1.x,acc);  acc=fmaf(dbp[5],w1.y,acc);  acc=fmaf(dbp[6],w1.z,acc);  acc=fmaf(dbp[7],w1.w,acc);
    acc=fmaf(dbp[8],w2.x,acc);  acc=fmaf(dbp[9],w2.y,acc);  acc=fmaf(dbp[10],w2.z,acc); acc=fmaf(dbp[11],w2.w,acc);
    acc=fmaf(dbp[12],w3.x,acc); acc=fmaf(dbp[13],w3.y,acc); acc=fmaf(dbp[14],w3.z,acc); acc=fmaf(dbp[15],w3.w,acc);
    us[ti2][d] = (acc > 20.f) ? acc : log1pf(__expf(acc));
  }
  __syncthreads();
  #pragma unroll
  for (int rr=0;rr<2;rr++){
    int d = tid + rr*256;
    float4 v0, v1;
    v0.x=us[0][d]; v0.y=us[1][d]; v0.z=us[2][d]; v0.w=us[3][d];
    v1.x=us[4][d]; v1.y=us[5][d]; v1.z=us[6][d]; v1.w=us[7][d];
    float* dp = g_dtt + ((size_t)(b*DI + d))*LL + l0;
    *(float4*)dp = v0; *(float4*)(dp+4) = v1;
  }
}

// ---------------- SSM chunked parallel scan: block = one (b,d) ----------------
__global__ void ssm_scan(const float* __restrict__ Alog, const float* __restrict__ Dp){
  __shared__ float sA[16][17], sB[16][17], sH[16][17];
  __shared__ float sv[256][17];
  const int bd = blockIdx.x;
  const int b = bd >> 9, d = bd & 511;
  const int tid = threadIdx.x;
  const int c = tid >> 4, s = tid & 15;
  const float As = -__expf(Alog[d*16 + s]);
  const float* dtp = g_dtt + ((size_t)(b*DI + d))*LL + c*16;
  const float* up  = g_ut  + ((size_t)(b*DI + d))*LL + c*16;
  const float* bcp = g_bc + ((size_t)(b*LL + c*16))*32 + s;
  float a[16], bv[16];
  #pragma unroll
  for (int i=0;i<16;i++){
    float dt = dtp[i], u = up[i];
    float Bm = bcp[i*32];
    a[i]  = __expf(dt * As);
    bv[i] = dt * u * Bm;
  }
  float Ap = 1.f, Bf = 0.f;
  #pragma unroll
  for (int i=0;i<16;i++){ Bf = fmaf(a[i], Bf, bv[i]); Ap *= a[i]; }
  sA[c][s] = Ap; sB[c][s] = Bf;
  __syncthreads();
  if (tid < 16){
    float h = 0.f;
    #pragma unroll
    for (int cc=0;cc<16;cc++){
      sH[cc][tid] = h;
      h = fmaf(sA[cc][tid], h, sB[cc][tid]);
    }
  }
  __syncthreads();
  float h = sH[c][s];
  #pragma unroll
  for (int i=0;i<16;i++){
    h = fmaf(a[i], h, bv[i]);
    float Cm = bcp[i*32 + 16];
    sv[c*16 + i][s] = h * Cm;
  }
  __syncthreads();
  float y = 0.f;
  #pragma unroll
  for (int ss=0;ss<16;ss++) y += sv[tid][ss];
  float u_t = g_ut[((size_t)(b*DI + d))*LL + tid];
  float zs  = g_zs[((size_t)(b*DI + d))*LL + tid];
  g_yt[((size_t)(b*DI + d))*LL + tid] = (y + u_t * Dp[d]) * zs;
}

// ---------------- y transpose: g_yt[b][d][t] -> row-major [b*L+t][d] ----------------
__global__ void ytr_kernel(float* __restrict__ gy){
  __shared__ float tile[32][33];
  int b = blockIdx.z; int t0 = blockIdx.x*32; int d0 = blockIdx.y*32;
  int tx = threadIdx.x, ty = threadIdx.y;   // 32 x 8
  #pragma unroll
  for (int i=0;i<32;i+=8)
    tile[ty+i][tx] = g_yt[((size_t)b*DI + d0+ty+i)*LL + t0+tx];
  __syncthreads();
  #pragma unroll
  for (int i=0;i<32;i+=8)
    gy[((size_t)b*LL + t0+ty+i)*DI + d0+tx] = tile[tx][ty+i];
}

// ---------------- feat[b,e,l] = h[b,l,e] ----------------
__global__ void feat_kernel(){
  __shared__ float tile[32][33];
  int b = blockIdx.z; int t0 = blockIdx.x*32; int e0 = blockIdx.y*32;
  int tx = threadIdx.x, ty = threadIdx.y;
  #pragma unroll
  for (int i=0;i<32;i+=8)
    tile[ty+i][tx] = g_h[((size_t)b*LL + t0+ty+i)*EE + e0+tx];
  __syncthreads();
  #pragma unroll
  for (int i=0;i<32;i+=8)
    g_feat[((size_t)b*EE + e0+ty+i)*LL + t0+tx] = tile[tx][ty+i];
}

// ---------------- ConvTranspose2d stride2 k2 ----------------
template<int C,int O,int OGRP,int GELU>
__global__ void convt_kernel(const float* __restrict__ x, const float* __restrict__ w,
                             const float* __restrict__ bias, float* __restrict__ out,
                             int Hin, int Win){
  int idx = blockIdx.x*blockDim.x + threadIdx.x;
  int w_ = idx % Win; int tmp = idx / Win;
  int h_ = tmp % Hin; tmp /= Hin;
  int og = tmp % (O/OGRP); int b = tmp / (O/OGRP);
  int o0 = og*OGRP;
  float acc[OGRP][4];
  #pragma unroll
  for (int g=0;g<OGRP;g++){
    float bvv = bias[o0+g];
    acc[g][0]=bvv; acc[g][1]=bvv; acc[g][2]=bvv; acc[g][3]=bvv;
  }
  const float* xp = x + ((size_t)b*C*Hin + h_)*Win + w_;
  const float* wp = w + o0*4;
  size_t xstride = (size_t)Hin*Win;
  #pragma unroll 4
  for (int c=0;c<C;c++){
    float xv = __ldg(xp + c*xstride);
    const float4* w4 = (const float4*)(wp + (size_t)c*O*4);
    #pragma unroll
    for (int g=0;g<OGRP;g++){
      float4 wt = __ldg(w4 + g);
      acc[g][0]=fmaf(xv,wt.x,acc[g][0]); acc[g][1]=fmaf(xv,wt.y,acc[g][1]);
      acc[g][2]=fmaf(xv,wt.z,acc[g][2]); acc[g][3]=fmaf(xv,wt.w,acc[g][3]);
    }
  }
  int Ho = 2*Hin, Wo = 2*Win;
  #pragma unroll
  for (int g=0;g<OGRP;g++){
    float r00=acc[g][0], r01=acc[g][1], r10=acc[g][2], r11=acc[g][3];
    if (GELU){ r00=geluf(r00); r01=geluf(r01); r10=geluf(r10); r11=geluf(r11); }
    float* op = out + (((size_t)b*O + o0+g)*Ho + 2*h_)*(size_t)Wo + 2*w_;
    *(float2*)op        = make_float2(r00,r01);
    *(float2*)(op + Wo) = make_float2(r10,r11);
  }
}

// ---------------- launch ----------------
extern "C" void kernel_launch(void* const* d_in, const int* in_sizes, int n_in,
                              void* d_out, int out_size){
  const float* x       = (const float*)d_in[0];
  const int*   t       = (const int*)d_in[1];
  const float* time_w1 = (const float*)d_in[2];
  const float* time_b1 = (const float*)d_in[3];
  const float* time_w2 = (const float*)d_in[4];
  const float* time_b2 = (const float*)d_in[5];
  const float* patch_w = (const float*)d_in[6];
  const float* patch_b = (const float*)d_in[7];
  const float* pos     = (const float*)d_in[8];
  const float* ln_g    = (const float*)d_in[9];
  const float* ln_b    = (const float*)d_in[10];
  const float* in_proj = (const float*)d_in[11];
  const float* conv_w  = (const float*)d_in[12];
  const float* conv_b  = (const float*)d_in[13];
  const float* x_proj  = (const float*)d_in[14];
  const float* dt_w    = (const float*)d_in[15];
  const float* dt_b    = (const float*)d_in[16];
  const float* A_log   = (const float*)d_in[17];
  const float* Dp      = (const float*)d_in[18];
  const float* out_proj= (const float*)d_in[19];
  const float* dw1 = (const float*)d_in[20];
  const float* db1 = (const float*)d_in[21];
  const float* dw2 = (const float*)d_in[22];
  const float* db2 = (const float*)d_in[23];
  const float* dw3 = (const float*)d_in[24];
  const float* db3 = (const float*)d_in[25];
  const float* dw4 = (const float*)d_in[26];
  const float* db4 = (const float*)d_in[27];

  float *p_patches,*p_h,*p_xz,*p_temb,*p_feat,*p_d1,*p_d2,*p_d3;
  cudaGetSymbolAddress((void**)&p_patches, g_patches);
  cudaGetSymbolAddress((void**)&p_h, g_h);
  cudaGetSymbolAddress((void**)&p_xz, g_xz);
  cudaGetSymbolAddress((void**)&p_temb, g_temb);
  cudaGetSymbolAddress((void**)&p_feat, g_feat);
  cudaGetSymbolAddress((void**)&p_d1, g_d1);
  cudaGetSymbolAddress((void**)&p_d2, g_d2);
  cudaGetSymbolAddress((void**)&p_d3, g_d3);

  cudaFuncSetAttribute(mma_gemm<1,0,1>, cudaFuncAttributeMaxDynamicSharedMemorySize, SMEM_BM64);
  cudaFuncSetAttribute(mma_gemm<2,1,0>, cudaFuncAttributeMaxDynamicSharedMemorySize, SMEM_BM128);
  cudaFuncSetAttribute(mma_gemm<1,0,2>, cudaFuncAttributeMaxDynamicSharedMemorySize, SMEM_BM64);

  time_emb_kernel<<<BB, EE>>>(t, time_w1, time_b1, time_w2, time_b2);
  patch_gather_kernel<<<(NTOK*512)/256, 256>>>(x);
  // patch embed: 2048x256x512, epi = bias+pos+temb  (BM=64 -> 128 blocks)
  mma_gemm<1,0,1><<<dim3(EE/64, NTOK/64), 256, SMEM_BM64>>>(
      p_patches, patch_w, nullptr, nullptr, patch_b, pos, p_temb, p_h, 512, EE);

  for (int i=0;i<DEPTH;i++){
    // in_proj with fused LN: 2048x1024x256 (BM=128 -> 256 blocks)
    mma_gemm<2,1,0><<<dim3(XZW/64, NTOK/128), 256, SMEM_BM128>>>(
        p_h, in_proj + (size_t)i*XZW*EE,
        ln_g + (size_t)i*EE, ln_b + (size_t)i*EE,
        nullptr, nullptr, nullptr, p_xz, EE, XZW);
    prep_kernel<<<NTOK/8, 256>>>(conv_w + (size_t)i*DI*DCN, conv_b + (size_t)i*DI,
                                 x_proj + (size_t)i*48*DI,
                                 dt_w + (size_t)i*DI*DTRN, dt_b + (size_t)i*DI);
    ssm_scan<<<BB*DI, 256>>>(A_log + (size_t)i*DI*DS, Dp + (size_t)i*DI);
    // transpose y to row-major (reuse g_patches)
    ytr_kernel<<<dim3(LL/32, DI/32, BB), dim3(32,8)>>>(p_patches);
    // out_proj + residual: 2048x256x512 (BM=64 -> 128 blocks)
    mma_gemm<1,0,2><<<dim3(EE/64, NTOK/64), 256, SMEM_BM64>>>(
        p_patches, out_proj + (size_t)i*EE*DI,
        nullptr, nullptr, nullptr, nullptr, nullptr, p_h, DI, EE);
  }

  feat_kernel<<<dim3(LL/32, EE/32, BB), dim3(32,8)>>>();
  convt_kernel<256,128,4,1><<<(BB*(128/4)*16*16)/256, 256>>>(p_feat, dw1, db1, p_d1, 16, 16);
  convt_kernel<128,64,4,1><<<(BB*(64/4)*32*32)/256, 256>>>(p_d1, dw2, db2, p_d2, 32, 32);
  convt_kernel<64,32,4,1><<<(BB*(32/4)*64*64)/256, 256>>>(p_d2, dw3, db3, p_d3, 64, 64);
  convt_kernel<32,1,1,0><<<(BB*1*128*128)/256, 256>>>(p_d3, dw4, db4, (float*)d_out, 128, 128);
}

// round 9
// speedup vs baseline: 1.4554x; 1.4554x over previous
#include <cuda_runtime.h>
#include <cuda_bf16.h>
#include <math.h>

#define BB 8
#define IMG 256
#define INCH 2
#define PSZ 16
#define EE 256
#define DEPTH 8
#define HPN 16
#define LL 256
#define DI 512
#define DS 16
#define DTRN 16
#define DCN 4
#define NTOK 2048          // B*L
#define XZW 1024           // 2*DI

// ---------------- scratch ----------------
__device__ float g_temb[BB*EE];
__device__ float g_h[NTOK*EE];
__device__ float g_patches[NTOK*512];   // also reused as row-major y after ssm
__device__ float g_xz[NTOK*XZW];
__device__ float g_ut[BB*DI*LL];    // u transposed [b][d][t]
__device__ float g_dtt[BB*DI*LL];   // dt transposed [b][d][t]
__device__ float g_zs[BB*DI*LL];    // silu(z) transposed [b][d][t]
__device__ float g_bc[NTOK*32];     // B[16],C[16] per token
__device__ float g_yt[BB*DI*LL];    // y transposed [b][d][t]
__device__ float g_feat[BB*EE*HPN*HPN];
__device__ float g_d1[BB*128*32*32];
__device__ float g_d2[BB*64*64*64];
__device__ float g_d3[BB*32*128*128];

__device__ __forceinline__ float geluf(float v){ return 0.5f*v*(1.0f+erff(v*0.70710678118654752f)); }
__device__ __forceinline__ float siluf(float v){ return v/(1.0f+__expf(-v)); }

__device__ __forceinline__ void mma16(float* d, const unsigned* a, unsigned b0, unsigned b1){
  asm volatile("mma.sync.aligned.m16n8k16.row.col.f32.bf16.bf16.f32 "
    "{%0,%1,%2,%3}, {%4,%5,%6,%7}, {%8,%9}, {%0,%1,%2,%3};"
    : "+f"(d[0]),"+f"(d[1]),"+f"(d[2]),"+f"(d[3])
    : "r"(a[0]),"r"(a[1]),"r"(a[2]),"r"(a[3]), "r"(b0),"r"(b1));
}

// split float4 (4 consecutive k = 2 kpairs) into interleaved {hi,lo,hi,lo} words; one STS.128
// widx must be the word index of kpair (k0/2), i.e. equal to the (even) k offset.
__device__ __forceinline__ void store_split(unsigned* base, int widx, float4 v){
  __nv_bfloat162 h0 = __floats2bfloat162_rn(v.x, v.y);
  __nv_bfloat162 h1 = __floats2bfloat162_rn(v.z, v.w);
  float r0 = v.x - __bfloat162float(h0.x);
  float r1 = v.y - __bfloat162float(h0.y);
  float r2 = v.z - __bfloat162float(h1.x);
  float r3 = v.w - __bfloat162float(h1.y);
  __nv_bfloat162 l0 = __floats2bfloat162_rn(r0, r1);
  __nv_bfloat162 l1 = __floats2bfloat162_rn(r2, r3);
  uint4 w;
  w.x = *(unsigned*)&h0; w.y = *(unsigned*)&l0;
  w.z = *(unsigned*)&h1; w.w = *(unsigned*)&l1;
  *(uint4*)(base + widx) = w;
}

// ---------------- time embedding ----------------
__global__ void time_emb_kernel(const int* __restrict__ t, const float* __restrict__ w1,
                                const float* __restrict__ b1, const float* __restrict__ w2,
                                const float* __restrict__ b2){
  __shared__ float hdn[EE];
  int b = blockIdx.x; int j = threadIdx.x;
  float tf = (float)t[b];
  hdn[j] = geluf(tf*w1[j] + b1[j]);
  __syncthreads();
  float acc = b2[j];
  #pragma unroll 8
  for (int k=0;k<EE;k++) acc = fmaf(hdn[k], w2[k*EE + j], acc);
  g_temb[b*EE + j] = acc;
}

// ---------------- im2col patch gather ----------------
__global__ void patch_gather_kernel(const float* __restrict__ x){
  int idx = blockIdx.x*blockDim.x + threadIdx.x;
  int k = idx & 511; int tok = idx >> 9;
  int l = tok & (LL-1); int b = tok >> 8;
  int c = k >> 8; int rem = k & 255; int p = rem >> 4; int q = rem & 15;
  int hp = l >> 4; int wp = l & 15;
  g_patches[idx] = x[(((size_t)(b*INCH + c))*IMG + hp*PSZ + p)*IMG + wp*PSZ + q];
}

// ================= bf16x3 tensor-core GEMM (interleaved hi/lo planes) =================
// C[M,N] = A[M,K] @ W[N,K]^T. Block (64*MTILES)x64, BK=32, 8 warps (4m x 2n), warp (16*MTILES)x32.
// smem word layout: idx(m,kp,plane) = m*40 + kp*2 + plane; plane0=hi bf16 pair, plane1=lo.
// Fragment loads are LDS.64 {hi,lo}; loader stores STS.128 per 4 k-values.
// ASRC: 0 = plain row-major A; 1 = fused LayerNorm on A rows (lng/lnb; requires MTILES=2)
// EPI : 0 = plain; 1 = +bias+pos+temb; 2 = += C (residual)
#define B_SZI (64*40)
#define SMEM_BM64  ((2*64*40 + 2*B_SZI)*4)
#define SMEM_BM128 ((2*128*40 + 2*B_SZI)*4 + 256*4)
template<int MTILES,int ASRC,int EPI>
__global__ void __launch_bounds__(256)
mma_gemm(const float* __restrict__ A, const float* __restrict__ W,
         const float* __restrict__ lng, const float* __restrict__ lnb,
         const float* __restrict__ bias, const float* __restrict__ pos,
         const float* __restrict__ temb, float* __restrict__ C,
         int K, int N)
{
  constexpr int BM = 64*MTILES;
  constexpr int A_SZI = BM*40;
  extern __shared__ unsigned smem_u[];
  unsigned* uA = smem_u;                         // [buf][m][kp][plane]
  unsigned* uB = smem_u + 2*A_SZI;               // [buf][n][kp][plane]
  float* s_mu = (float*)(smem_u + 2*A_SZI + 2*B_SZI);
  float* s_rs = s_mu + 128;

  const int tid = threadIdx.x;
  const int m0 = blockIdx.y*BM, n0 = blockIdx.x*64;

  if (ASRC==1){
    int r = tid>>1, hf = tid&1;
    const float4* row = (const float4*)(A + (size_t)(m0+r)*K + hf*(K/2));
    float s=0.f, sq=0.f;
    for (int i=0;i<K/8;i++){ float4 v=row[i];
      s += v.x+v.y+v.z+v.w; sq += v.x*v.x+v.y*v.y+v.z*v.z+v.w*v.w; }
    s  += __shfl_xor_sync(0xffffffffu, s, 1);
    sq += __shfl_xor_sync(0xffffffffu, sq, 1);
    if (!hf){
      float muv = s/(float)K;
      float var = sq/(float)K - muv*muv;
      s_mu[r]=muv; s_rs[r]=rsqrtf(var+1e-5f);
    }
    __syncthreads();
  }

  // loader coords
  const int amr = tid>>3;            // A row base (0..31), +i*32
  const int akc = (tid&7)*4;         // k offset within chunk (0,4,..,28); also word idx of kpair group
  const int NK = K/32;

  // initial chunk 0 into buf 0
  {
    float4 g4, b4;
    if (ASRC==1){ g4 = *(const float4*)(lng+akc); b4 = *(const float4*)(lnb+akc); }
    #pragma unroll
    for (int i=0;i<BM/32;i++){
      int m = amr + i*32;
      float4 v = *(const float4*)(A + (size_t)(m0+m)*K + akc);
      if (ASRC==1){
        float mu = s_mu[m], rs = s_rs[m];
        v.x=(v.x-mu)*rs*g4.x+b4.x; v.y=(v.y-mu)*rs*g4.y+b4.y;
        v.z=(v.z-mu)*rs*g4.z+b4.z; v.w=(v.w-mu)*rs*g4.w+b4.w;
      }
      store_split(uA, m*40 + akc, v);
    }
    #pragma unroll
    for (int i=0;i<2;i++){
      int p = tid + i*256;
      int n = p>>3, kc4 = (p&7)*4;
      float4 v = *(const float4*)(W + (size_t)(n0+n)*K + kc4);
      store_split(uB, n*40 + kc4, v);
    }
  }
  __syncthreads();

  const int lane = tid&31, wid = tid>>5;
  const int wm = (wid>>1)*(16*MTILES), wn = (wid&1)*32;
  const int g = lane>>2, tg = lane&3;
  float acc[MTILES][4][4] = {};

  float4 pa[BM/32], pb[2], pg4, pb4;
  for (int ks=0; ks<NK; ks++){
    const int buf = ks&1;
    if (ks+1 < NK){
      int k0 = (ks+1)*32;
      if (ASRC==1){ pg4 = *(const float4*)(lng+k0+akc); pb4 = *(const float4*)(lnb+k0+akc); }
      #pragma unroll
      for (int i=0;i<BM/32;i++)
        pa[i] = *(const float4*)(A + (size_t)(m0+amr+i*32)*K + k0 + akc);
      #pragma unroll
      for (int i=0;i<2;i++){
        int p = tid + i*256;
        pb[i] = *(const float4*)(W + (size_t)(n0+(p>>3))*K + k0 + (p&7)*4);
      }
    }
    const unsigned* As_ = uA + buf*A_SZI;
    const unsigned* Bs_ = uB + buf*B_SZI;
    #pragma unroll
    for (int h=0; h<2; h++){
      const int kb = h*8;
      // B fragments: per ntile two LDS.64 -> {bh0,bl0},{bh1,bl1}
      unsigned bh[4][2], bl[4][2];
      #pragma unroll
      for (int nt=0;nt<4;nt++){
        int nb = wn + nt*8 + g;
        uint2 p0 = *(const uint2*)&Bs_[nb*40 + (kb+tg)*2];
        uint2 p1 = *(const uint2*)&Bs_[nb*40 + (kb+tg+4)*2];
        bh[nt][0]=p0.x; bl[nt][0]=p0.y;
        bh[nt][1]=p1.x; bl[nt][1]=p1.y;
      }
      #pragma unroll
      for (int mt=0;mt<MTILES;mt++){
        int mb = wm + mt*16;
        uint2 q00 = *(const uint2*)&As_[(mb+g  )*40 + (kb+tg)*2];
        uint2 q10 = *(const uint2*)&As_[(mb+g+8)*40 + (kb+tg)*2];
        uint2 q01 = *(const uint2*)&As_[(mb+g  )*40 + (kb+tg+4)*2];
        uint2 q11 = *(const uint2*)&As_[(mb+g+8)*40 + (kb+tg+4)*2];
        unsigned ah[4] = {q00.x, q10.x, q01.x, q11.x};
        unsigned al[4] = {q00.y, q10.y, q01.y, q11.y};
        #pragma unroll
        for (int nt=0;nt<4;nt++){
          mma16(acc[mt][nt], ah, bh[nt][0], bh[nt][1]);
          mma16(acc[mt][nt], al, bh[nt][0], bh[nt][1]);
          mma16(acc[mt][nt], ah, bl[nt][0], bl[nt][1]);
        }
      }
    }
    if (ks+1 < NK){
      unsigned* dA = uA + (buf^1)*A_SZI;
      unsigned* dB = uB + (buf^1)*B_SZI;
      #pragma unroll
      for (int i=0;i<BM/32;i++){
        int m = amr + i*32;
        float4 v = pa[i];
        if (ASRC==1){
          float mu = s_mu[m], rs = s_rs[m];
          v.x=(v.x-mu)*rs*pg4.x+pb4.x; v.y=(v.y-mu)*rs*pg4.y+pb4.y;
          v.z=(v.z-mu)*rs*pg4.z+pb4.z; v.w=(v.w-mu)*rs*pg4.w+pb4.w;
        }
        store_split(dA, m*40 + akc, v);
      }
      #pragma unroll
      for (int i=0;i<2;i++){
        int p = tid + i*256;
        store_split(dB, (p>>3)*40 + (p&7)*4, pb[i]);
      }
    }
    __syncthreads();
  }

  // epilogue
  #pragma unroll
  for (int mt=0;mt<MTILES;mt++){
    #pragma unroll
    for (int nt=0;nt<4;nt++){
      int row = m0 + wm + mt*16 + g;
      int col = n0 + wn + nt*8 + tg*2;
      float2 v0 = make_float2(acc[mt][nt][0], acc[mt][nt][1]);
      float2 v1 = make_float2(acc[mt][nt][2], acc[mt][nt][3]);
      if (EPI==1){
        int l0i = row & 255, b0i = row >> 8;
        int l1i = (row+8) & 255, b1i = (row+8) >> 8;
        v0.x += bias[col]   + pos[(size_t)l0i*EE+col]   + temb[(size_t)b0i*EE+col];
        v0.y += bias[col+1] + pos[(size_t)l0i*EE+col+1] + temb[(size_t)b0i*EE+col+1];
        v1.x += bias[col]   + pos[(size_t)l1i*EE+col]   + temb[(size_t)b1i*EE+col];
        v1.y += bias[col+1] + pos[(size_t)l1i*EE+col+1] + temb[(size_t)b1i*EE+col+1];
      } else if (EPI==2){
        float2 o0 = *(float2*)(C + (size_t)row*N + col);
        float2 o1 = *(float2*)(C + (size_t)(row+8)*N + col);
        v0.x += o0.x; v0.y += o0.y; v1.x += o1.x; v1.y += o1.y;
      }
      *(float2*)(C + (size_t)row*N + col) = v0;
      *(float2*)(C + (size_t)(row+8)*N + col) = v1;
    }
  }
}

// ---------------- fused prep: causal-conv+SiLU, z-SiLU, x_proj, dt; transposed stores ----
__global__ void prep_kernel(const float* __restrict__ cw, const float* __restrict__ cb,
                            const float* __restrict__ xw,   // [48][512]
                            const float* __restrict__ dtw,  // [512][16]
                            const float* __restrict__ dtb){ // [512]
  __shared__ float us[8][513];
  __shared__ float pool[48*129];
  __shared__ float dbc_s[8][52];
  const int tid = threadIdx.x;            // 256
  const int b  = blockIdx.x >> 5;
  const int l0 = (blockIdx.x & 31) * 8;
  float* zsm = pool;
  #pragma unroll
  for (int r=0;r<16;r++){
    int idx = r*256 + tid;
    int d  = idx & 511;
    int ti = idx >> 9;
    int l  = l0 + ti;
    float acc = cb[d];
    #pragma unroll
    for (int j=0;j<4;j++){
      int ls = l + j - 3;
      if (ls >= 0) acc = fmaf(g_xz[((size_t)(b*LL + ls))*XZW + d], cw[d*4 + j], acc);
    }
    us[ti][d] = siluf(acc);
    float z = g_xz[((size_t)(b*LL + l))*XZW + DI + d];
    zsm[ti*516 + d] = siluf(z);
  }
  __syncthreads();
  #pragma unroll
  for (int rr=0;rr<2;rr++){
    int d = tid + rr*256;
    float4 v0, v1, w0, w1;
    v0.x=us[0][d]; v0.y=us[1][d]; v0.z=us[2][d]; v0.w=us[3][d];
    v1.x=us[4][d]; v1.y=us[5][d]; v1.z=us[6][d]; v1.w=us[7][d];
    w0.x=zsm[0*516+d]; w0.y=zsm[1*516+d]; w0.z=zsm[2*516+d]; w0.w=zsm[3*516+d];
    w1.x=zsm[4*516+d]; w1.y=zsm[5*516+d]; w1.z=zsm[6*516+d]; w1.w=zsm[7*516+d];
    float* up = g_ut + ((size_t)(b*DI + d))*LL + l0;
    *(float4*)up = v0; *(float4*)(up+4) = v1;
    float* zp = g_zs + ((size_t)(b*DI + d))*LL + l0;
    *(float4*)zp = w0; *(float4*)(zp+4) = w1;
  }
  const int ti = tid >> 5, lane = tid & 31;
  float accA = 0.f, accB = 0.f;
  for (int kt=0;kt<4;kt++){
    __syncthreads();
    #pragma unroll
    for (int i=0;i<6;i++){
      int f = (tid + i*256)*4;
      int j = f >> 7, c = f & 127;
      float4 v = *(const float4*)(xw + (size_t)j*DI + kt*128 + c);
      pool[j*129+c]=v.x; pool[j*129+c+1]=v.y; pool[j*129+c+2]=v.z; pool[j*129+c+3]=v.w;
    }
    __syncthreads();
    #pragma unroll 4
    for (int c=0;c<128;c++){
      float a = us[ti][kt*128 + c];
      accA = fmaf(a, pool[lane*129 + c], accA);
      if (lane < 16) accB = fmaf(a, pool[(32+lane)*129 + c], accB);
    }
  }
  __syncthreads();
  dbc_s[ti][lane] = accA;
  if (lane < 16) dbc_s[ti][32 + lane] = accB;
  __syncthreads();
  {
    int tti = tid >> 5, jj = tid & 31;
    g_bc[((size_t)(b*LL) + l0 + tti)*32 + jj] = dbc_s[tti][16 + jj];
  }
  #pragma unroll
  for (int r=0;r<16;r++){
    int idx = r*256 + tid;
    int d  = idx & 511;
    int ti2 = idx >> 9;
    const float* dbp = dbc_s[ti2];
    const float4* dw4 = (const float4*)(dtw + (size_t)d*16);
    float4 w0 = dw4[0], w1 = dw4[1], w2 = dw4[2], w3 = dw4[3];
    float acc = dtb[d];
    acc=fmaf(dbp[0],w0.x,acc);  acc=fmaf(dbp[1],w0.y,acc);  acc=fmaf(dbp[2],w0.z,acc);  acc=fmaf(dbp[3],w0.w,acc);
    acc=fmaf(dbp[4],w1.x,acc);  acc=fmaf(dbp[5],w1.y,acc);  acc=fmaf(dbp[6],w1.z,acc);  acc=fmaf(dbp[7],w1.w,acc);
    acc=fmaf(dbp[8],w2.x,acc);  acc=fmaf(dbp[9],w2.y,acc);  acc=fmaf(dbp[10],w2.z,acc); acc=fmaf(dbp[11],w2.w,acc);
    acc=fmaf(dbp[12],w3.x,acc); acc=fmaf(dbp[13],w3.y,acc); acc=fmaf(dbp[14],w3.z,acc); acc=fmaf(dbp[15],w3.w,acc);
    us[ti2][d] = (acc > 20.f) ? acc : log1pf(__expf(acc));
  }
  __syncthreads();
  #pragma unroll
  for (int rr=0;rr<2;rr++){
    int d = tid + rr*256;
    float4 v0, v1;
    v0.x=us[0][d]; v0.y=us[1][d]; v0.z=us[2][d]; v0.w=us[3][d];
    v1.x=us[4][d]; v1.y=us[5][d]; v1.z=us[6][d]; v1.w=us[7][d];
    float* dp = g_dtt + ((size_t)(b*DI + d))*LL + l0;
    *(float4*)dp = v0; *(float4*)(dp+4) = v1;
  }
}

// ---------------- SSM chunked parallel scan: block = one (b,d) ----------------
__global__ void ssm_scan(const float* __restrict__ Alog, const float* __restrict__ Dp){
  __shared__ float sA[16][17], sB[16][17], sH[16][17];
  __shared__ float sv[256][17];
  const int bd = blockIdx.x;
  const int b = bd >> 9, d = bd & 511;
  const int tid = threadIdx.x;
  const int c = tid >> 4, s = tid & 15;
  const float As = -__expf(Alog[d*16 + s]);
  const float* dtp = g_dtt + ((size_t)(b*DI + d))*LL + c*16;
  const float* up  = g_ut  + ((size_t)(b*DI + d))*LL + c*16;
  const float* bcp = g_bc + ((size_t)(b*LL + c*16))*32 + s;
  float a[16], bv[16];
  #pragma unroll
  for (int i=0;i<16;i++){
    float dt = dtp[i], u = up[i];
    float Bm = bcp[i*32];
    a[i]  = __expf(dt * As);
    bv[i] = dt * u * Bm;
  }
  float Ap = 1.f, Bf = 0.f;
  #pragma unroll
  for (int i=0;i<16;i++){ Bf = fmaf(a[i], Bf, bv[i]); Ap *= a[i]; }
  sA[c][s] = Ap; sB[c][s] = Bf;
  __syncthreads();
  if (tid < 16){
    float h = 0.f;
    #pragma unroll
    for (int cc=0;cc<16;cc++){
      sH[cc][tid] = h;
      h = fmaf(sA[cc][tid], h, sB[cc][tid]);
    }
  }
  __syncthreads();
  float h = sH[c][s];
  #pragma unroll
  for (int i=0;i<16;i++){
    h = fmaf(a[i], h, bv[i]);
    float Cm = bcp[i*32 + 16];
    sv[c*16 + i][s] = h * Cm;
  }
  __syncthreads();
  float y = 0.f;
  #pragma unroll
  for (int ss=0;ss<16;ss++) y += sv[tid][ss];
  float u_t = g_ut[((size_t)(b*DI + d))*LL + tid];
  float zs  = g_zs[((size_t)(b*DI + d))*LL + tid];
  g_yt[((size_t)(b*DI + d))*LL + tid] = (y + u_t * Dp[d]) * zs;
}

// ---------------- y transpose: g_yt[b][d][t] -> row-major [b*L+t][d] ----------------
__global__ void ytr_kernel(float* __restrict__ gy){
  __shared__ float tile[32][33];
  int b = blockIdx.z; int t0 = blockIdx.x*32; int d0 = blockIdx.y*32;
  int tx = threadIdx.x, ty = threadIdx.y;   // 32 x 8
  #pragma unroll
  for (int i=0;i<32;i+=8)
    tile[ty+i][tx] = g_yt[((size_t)b*DI + d0+ty+i)*LL + t0+tx];
  __syncthreads();
  #pragma unroll
  for (int i=0;i<32;i+=8)
    gy[((size_t)b*LL + t0+ty+i)*DI + d0+tx] = tile[tx][ty+i];
}

// ---------------- feat[b,e,l] = h[b,l,e] ----------------
__global__ void feat_kernel(){
  __shared__ float tile[32][33];
  int b = blockIdx.z; int t0 = blockIdx.x*32; int e0 = blockIdx.y*32;
  int tx = threadIdx.x, ty = threadIdx.y;
  #pragma unroll
  for (int i=0;i<32;i+=8)
    tile[ty+i][tx] = g_h[((size_t)b*LL + t0+ty+i)*EE + e0+tx];
  __syncthreads();
  #pragma unroll
  for (int i=0;i<32;i+=8)
    g_feat[((size_t)b*EE + e0+ty+i)*LL + t0+tx] = tile[tx][ty+i];
}

// ---------------- ConvTranspose2d stride2 k2 ----------------
template<int C,int O,int OGRP,int GELU>
__global__ void convt_kernel(const float* __restrict__ x, const float* __restrict__ w,
                             const float* __restrict__ bias, float* __restrict__ out,
                             int Hin, int Win){
  int idx = blockIdx.x*blockDim.x + threadIdx.x;
  int w_ = idx % Win; int tmp = idx / Win;
  int h_ = tmp % Hin; tmp /= Hin;
  int og = tmp % (O/OGRP); int b = tmp / (O/OGRP);
  int o0 = og*OGRP;
  float acc[OGRP][4];
  #pragma unroll
  for (int g=0;g<OGRP;g++){
    float bvv = bias[o0+g];
    acc[g][0]=bvv; acc[g][1]=bvv; acc[g][2]=bvv; acc[g][3]=bvv;
  }
  const float* xp = x + ((size_t)b*C*Hin + h_)*Win + w_;
  const float* wp = w + o0*4;
  size_t xstride = (size_t)Hin*Win;
  #pragma unroll 4
  for (int c=0;c<C;c++){
    float xv = __ldg(xp + c*xstride);
    const float4* w4 = (const float4*)(wp + (size_t)c*O*4);
    #pragma unroll
    for (int g=0;g<OGRP;g++){
      float4 wt = __ldg(w4 + g);
      acc[g][0]=fmaf(xv,wt.x,acc[g][0]); acc[g][1]=fmaf(xv,wt.y,acc[g][1]);
      acc[g][2]=fmaf(xv,wt.z,acc[g][2]); acc[g][3]=fmaf(xv,wt.w,acc[g][3]);
    }
  }
  int Ho = 2*Hin, Wo = 2*Win;
  #pragma unroll
  for (int g=0;g<OGRP;g++){
    float r00=acc[g][0], r01=acc[g][1], r10=acc[g][2], r11=acc[g][3];
    if (GELU){ r00=geluf(r00); r01=geluf(r01); r10=geluf(r10); r11=geluf(r11); }
    float* op = out + (((size_t)b*O + o0+g)*Ho + 2*h_)*(size_t)Wo + 2*w_;
    *(float2*)op        = make_float2(r00,r01);
    *(float2*)(op + Wo) = make_float2(r10,r11);
  }
}

// ---------------- launch ----------------
extern "C" void kernel_launch(void* const* d_in, const int* in_sizes, int n_in,
                              void* d_out, int out_size){
  const float* x       = (const float*)d_in[0];
  const int*   t       = (const int*)d_in[1];
  const float* time_w1 = (const float*)d_in[2];
  const float* time_b1 = (const float*)d_in[3];
  const float* time_w2 = (const float*)d_in[4];
  const float* time_b2 = (const float*)d_in[5];
  const float* patch_w = (const float*)d_in[6];
  const float* patch_b = (const float*)d_in[7];
  const float* pos     = (const float*)d_in[8];
  const float* ln_g    = (const float*)d_in[9];
  const float* ln_b    = (const float*)d_in[10];
  const float* in_proj = (const float*)d_in[11];
  const float* conv_w  = (const float*)d_in[12];
  const float* conv_b  = (const float*)d_in[13];
  const float* x_proj  = (const float*)d_in[14];
  const float* dt_w    = (const float*)d_in[15];
  const float* dt_b    = (const float*)d_in[16];
  const float* A_log   = (const float*)d_in[17];
  const float* Dp      = (const float*)d_in[18];
  const float* out_proj= (const float*)d_in[19];
  const float* dw1 = (const float*)d_in[20];
  const float* db1 = (const float*)d_in[21];
  const float* dw2 = (const float*)d_in[22];
  const float* db2 = (const float*)d_in[23];
  const float* dw3 = (const float*)d_in[24];
  const float* db3 = (const float*)d_in[25];
  const float* dw4 = (const float*)d_in[26];
  const float* db4 = (const float*)d_in[27];

  float *p_patches,*p_h,*p_xz,*p_temb,*p_feat,*p_d1,*p_d2,*p_d3;
  cudaGetSymbolAddress((void**)&p_patches, g_patches);
  cudaGetSymbolAddress((void**)&p_h, g_h);
  cudaGetSymbolAddress((void**)&p_xz, g_xz);
  cudaGetSymbolAddress((void**)&p_temb, g_temb);
  cudaGetSymbolAddress((void**)&p_feat, g_feat);
  cudaGetSymbolAddress((void**)&p_d1, g_d1);
  cudaGetSymbolAddress((void**)&p_d2, g_d2);
  cudaGetSymbolAddress((void**)&p_d3, g_d3);

  cudaFuncSetAttribute(mma_gemm<1,0,1>, cudaFuncAttributeMaxDynamicSharedMemorySize, SMEM_BM64);
  cudaFuncSetAttribute(mma_gemm<2,1,0>, cudaFuncAttributeMaxDynamicSharedMemorySize, SMEM_BM128);
  cudaFuncSetAttribute(mma_gemm<1,0,2>, cudaFuncAttributeMaxDynamicSharedMemorySize, SMEM_BM64);

  time_emb_kernel<<<BB, EE>>>(t, time_w1, time_b1, time_w2, time_b2);
  patch_gather_kernel<<<(NTOK*512)/256, 256>>>(x);
  // patch embed: 2048x256x512, epi = bias+pos+temb  (BM=64 -> 128 blocks)
  mma_gemm<1,0,1><<<dim3(EE/64, NTOK/64), 256, SMEM_BM64>>>(
      p_patches, patch_w, nullptr, nullptr, patch_b, pos, p_temb, p_h, 512, EE);

  for (int i=0;i<DEPTH;i++){
    // in_proj with fused LN: 2048x1024x256 (BM=128 -> 256 blocks)
    mma_gemm<2,1,0><<<dim3(XZW/64, NTOK/128), 256, SMEM_BM128>>>(
        p_h, in_proj + (size_t)i*XZW*EE,
        ln_g + (size_t)i*EE, ln_b + (size_t)i*EE,
        nullptr, nullptr, nullptr, p_xz, EE, XZW);
    prep_kernel<<<NTOK/8, 256>>>(conv_w + (size_t)i*DI*DCN, conv_b + (size_t)i*DI,
                                 x_proj + (size_t)i*48*DI,
                                 dt_w + (size_t)i*DI*DTRN, dt_b + (size_t)i*DI);
    ssm_scan<<<BB*DI, 256>>>(A_log + (size_t)i*DI*DS, Dp + (size_t)i*DI);
    // transpose y to row-major (reuse g_patches)
    ytr_kernel<<<dim3(LL/32, DI/32, BB), dim3(32,8)>>>(p_patches);
    // out_proj + residual: 2048x256x512 (BM=64 -> 128 blocks)
    mma_gemm<1,0,2><<<dim3(EE/64, NTOK/64), 256, SMEM_BM64>>>(
        p_patches, out_proj + (size_t)i*EE*DI,
        nullptr, nullptr, nullptr, nullptr, nullptr, p_h, DI, EE);
  }

  feat_kernel<<<dim3(LL/32, EE/32, BB), dim3(32,8)>>>();
  convt_kernel<256,128,4,1><<<(BB*(128/4)*16*16)/256, 256>>>(p_feat, dw1, db1, p_d1, 16, 16);
  convt_kernel<128,64,4,1><<<(BB*(64/4)*32*32)/256, 256>>>(p_d1, dw2, db2, p_d2, 32, 32);
  convt_kernel<64,32,4,1><<<(BB*(32/4)*64*64)/256, 256>>>(p_d2, dw3, db3, p_d3, 64, 64);
  convt_kernel<32,1,1,0><<<(BB*1*128*128)/256, 256>>>(p_d3, dw4, db4, (float*)d_out, 128, 128);
}